// round 4
// baseline (speedup 1.0000x reference)
#include <cuda_runtime.h>

// Fixed shapes: B=32, C=68, H=128, W=128
#define H 128
#define W 128
#define TILE 64                      // output rows per block
#define SROWS (TILE + 2)             // +1 halo row each side
#define TILES_PER_PLANE (H / TILE)   // 2
#define NPLANES (32 * 68)            // 2176
#define NBLOCKS (NPLANES * TILES_PER_PLANE)  // 4352
#define N_ELEMS 35651584.0

#define OMEGA 14.0f
#define THETA 0.5f
#define MASK_THRESHOLD 0.2f
#define LN2 0.6931471805599453f

__device__ float g_partials[NBLOCKS];
__device__ unsigned int g_count = 0;

__device__ __forceinline__ float ex2a(float x){ float r; asm("ex2.approx.ftz.f32 %0,%1;" : "=f"(r) : "f"(x)); return r; }
__device__ __forceinline__ float lg2a(float x){ float r; asm("lg2.approx.ftz.f32 %0,%1;" : "=f"(r) : "f"(x)); return r; }
__device__ __forceinline__ float rcpa(float x){ float r; asm("rcp.approx.ftz.f32 %0,%1;" : "=f"(r) : "f"(x)); return r; }

// horizontal 3-max over 4 columns: v = cols [4c..4c+3], l = col 4c-1, r = col 4c+4
__device__ __forceinline__ float4 hmax4(float4 v, float l, float r) {
    float4 h;
    h.x = fmaxf(l,   fmaxf(v.x, v.y));
    h.y = fmaxf(v.x, fmaxf(v.y, v.z));
    h.z = fmaxf(v.y, fmaxf(v.z, v.w));
    h.w = fmaxf(fmaxf(v.z, v.w), r);
    return h;
}

// unified AWing loss (branchless, exact for both reference branches):
//   t = min(diff, theta);  x = t^ay  (== diff^ay if diff<theta, == 0.5^ay else)
//   loss = omega*ln(1+x) + 2*omega*ay*x/(1+x) * max(diff-theta, 0)
__device__ __forceinline__ float awing_elem(float p, float y) {
    float ay   = 2.1f - y;
    float diff = fabsf(p - y);
    float t    = fminf(diff, THETA);
    float x    = ex2a(ay * lg2a(t));
    float l1   = lg2a(1.0f + x) * LN2;
    float dm   = fmaxf(diff - THETA, 0.0f);
    return OMEGA * l1 + 28.0f * ay * x * rcpa(1.0f + x) * dm;
}

__global__ __launch_bounds__(256)
void awing_fused_kernel(const float* __restrict__ pred,
                        const float* __restrict__ targ,
                        float* __restrict__ out)
{
    __shared__ float s[SROWS * W];     // 66*128*4 = 33792 B
    __shared__ float ws[8];
    __shared__ bool  isLast;

    const int bx      = blockIdx.x;
    const int plane   = bx >> 1;
    const int rowBase = (bx & 1) * TILE;
    const int tid     = threadIdx.x;
    const int tx      = tid & 31;      // column group: cols [4tx .. 4tx+3]
    const int ty      = tid >> 5;      // row stripe: rows [ty*8 .. ty*8+7]

    const float* tp = targ + (size_t)plane * (H * W);
    const float* pp = pred + (size_t)plane * (H * W);

    // ---- fill smem rows [rowBase-1 .. rowBase+TILE] (clamped) as float4 ----
    #pragma unroll
    for (int i = tid; i < SROWS * (W / 4); i += 256) {
        int r = i >> 5;
        int g = rowBase - 1 + r;
        g = max(0, min(H - 1, g));
        reinterpret_cast<float4*>(s)[i] =
            *reinterpret_cast<const float4*>(tp + g * W + ((i & 31) << 2));
    }
    __syncthreads();

    const int c0 = tx << 2;
    const int cl = max(c0 - 1, 0);
    const int cr = min(c0 + 4, W - 1);
    const int lr0 = ty * 8;            // first output row (tile-local)

    // ring init: smem row sr holds tile row sr-1
    float4 v0 = *reinterpret_cast<const float4*>(s + lr0 * W + c0);
    float4 hm0 = hmax4(v0, s[lr0 * W + cl], s[lr0 * W + cr]);
    float4 v1 = *reinterpret_cast<const float4*>(s + (lr0 + 1) * W + c0);
    float4 hm1 = hmax4(v1, s[(lr0 + 1) * W + cl], s[(lr0 + 1) * W + cr]);

    float acc = 0.0f;
    const float* prow = pp + (rowBase + lr0) * W + c0;

    #pragma unroll
    for (int k = 0; k < 8; k++) {
        const int sr2 = (lr0 + k + 2) * W;
        float4 v2  = *reinterpret_cast<const float4*>(s + sr2 + c0);
        float4 hm2 = hmax4(v2, s[sr2 + cl], s[sr2 + cr]);

        float4 p = *reinterpret_cast<const float4*>(prow);
        prow += W;

        float dx = fmaxf(fmaxf(hm0.x, hm1.x), hm2.x);
        float dy = fmaxf(fmaxf(hm0.y, hm1.y), hm2.y);
        float dz = fmaxf(fmaxf(hm0.z, hm1.z), hm2.z);
        float dw = fmaxf(fmaxf(hm0.w, hm1.w), hm2.w);

        float lx = awing_elem(p.x, v1.x);
        float ly = awing_elem(p.y, v1.y);
        float lz = awing_elem(p.z, v1.z);
        float lw = awing_elem(p.w, v1.w);

        acc += lx * ((dx > MASK_THRESHOLD) ? 11.0f : 1.0f);
        acc += ly * ((dy > MASK_THRESHOLD) ? 11.0f : 1.0f);
        acc += lz * ((dz > MASK_THRESHOLD) ? 11.0f : 1.0f);
        acc += lw * ((dw > MASK_THRESHOLD) ? 11.0f : 1.0f);

        hm0 = hm1; hm1 = hm2; v1 = v2;
    }

    // ---- deterministic block reduction ----
    #pragma unroll
    for (int o = 16; o; o >>= 1)
        acc += __shfl_down_sync(0xffffffffu, acc, o);
    if (tx == 0) ws[ty] = acc;
    __syncthreads();
    if (tid == 0) {
        float t = ((ws[0] + ws[1]) + (ws[2] + ws[3]))
                + ((ws[4] + ws[5]) + (ws[6] + ws[7]));
        g_partials[bx] = t;
        __threadfence();
        unsigned v = atomicAdd(&g_count, 1u);
        isLast = (v == NBLOCKS - 1);
    }
    __syncthreads();

    // ---- last block finishes the global mean (deterministic: fixed order) ----
    if (isLast) {
        __shared__ double sd[8];
        double a = 0.0;
        const float4* gp4 = reinterpret_cast<const float4*>(g_partials);
        #pragma unroll
        for (int i = tid; i < NBLOCKS / 4; i += 256) {
            float4 v = gp4[i];
            a += (double)v.x + (double)v.y + (double)v.z + (double)v.w;
        }
        #pragma unroll
        for (int o = 16; o; o >>= 1)
            a += __shfl_down_sync(0xffffffffu, a, o);
        if (tx == 0) sd[ty] = a;
        __syncthreads();
        if (tid == 0) {
            double t = ((sd[0] + sd[1]) + (sd[2] + sd[3]))
                     + ((sd[4] + sd[5]) + (sd[6] + sd[7]));
            out[0] = (float)(t / N_ELEMS);
            g_count = 0;   // reset for next graph replay
        }
    }
}

extern "C" void kernel_launch(void* const* d_in, const int* in_sizes, int n_in,
                              void* d_out, int out_size)
{
    const float* pred = (const float*)d_in[0];
    const float* targ = (const float*)d_in[1];

    awing_fused_kernel<<<NBLOCKS, 256>>>(pred, targ, (float*)d_out);
}

// round 5
// speedup vs baseline: 1.0364x; 1.0364x over previous
#include <cuda_runtime.h>

// Fixed shapes: B=32, C=68, H=128, W=128
#define H 128
#define W 128
#define NPLANES (32 * 68)        // 2176 blocks, one plane per block
#define STRIP 16                 // rows per warp (8 warps * 16 = 128)
#define N_ELEMS 35651584.0

#define OMEGA 14.0f
#define THETA 0.5f
#define MASK_THRESHOLD 0.2f
#define LN2 0.6931471805599453f
#define FULL 0xffffffffu

__device__ float g_partials[NPLANES];

__device__ __forceinline__ float ex2a(float x){ float r; asm("ex2.approx.ftz.f32 %0,%1;" : "=f"(r) : "f"(x)); return r; }
__device__ __forceinline__ float lg2a(float x){ float r; asm("lg2.approx.ftz.f32 %0,%1;" : "=f"(r) : "f"(x)); return r; }
__device__ __forceinline__ float rcpa(float x){ float r; asm("rcp.approx.ftz.f32 %0,%1;" : "=f"(r) : "f"(x)); return r; }

// Horizontal 3-max across the warp-wide row. v = this lane's 4 cols.
// Left/right neighbors come via shfl; boundary lanes clamp (symmetric pad==clamp).
__device__ __forceinline__ float4 hmax4_warp(float4 v, int lane) {
    float l = __shfl_up_sync(FULL, v.w, 1);    // col 4*lane-1
    float r = __shfl_down_sync(FULL, v.x, 1);  // col 4*lane+4
    if (lane == 0)  l = v.x;                   // clamp: left of col0 is col0
    if (lane == 31) r = v.w;                   // clamp: right of col127 is col127
    float4 h;
    h.x = fmaxf(l,   fmaxf(v.x, v.y));
    h.y = fmaxf(v.x, fmaxf(v.y, v.z));
    h.z = fmaxf(v.y, fmaxf(v.z, v.w));
    h.w = fmaxf(fmaxf(v.z, v.w), r);
    return h;
}

// Unified AWing loss (branchless, algebraically identical to both ref branches):
//   t = min(diff, theta);  x = t^ay  (== diff^ay if diff<theta, == 0.5^ay else)
//   loss = omega*ln(1+x) + 2*omega*ay*x/(1+x) * max(diff-theta, 0)
__device__ __forceinline__ float awing_elem(float p, float y) {
    float ay   = 2.1f - y;
    float diff = fabsf(p - y);
    float t    = fminf(diff, THETA);
    float x    = ex2a(ay * lg2a(t));
    float l1   = lg2a(1.0f + x) * LN2;
    float dm   = fmaxf(diff - THETA, 0.0f);
    return OMEGA * l1 + 28.0f * ay * x * rcpa(1.0f + x) * dm;
}

__global__ __launch_bounds__(256)
void awing_main_kernel(const float* __restrict__ pred,
                       const float* __restrict__ targ)
{
    __shared__ float ws[8];

    const int plane = blockIdx.x;
    const int tid   = threadIdx.x;
    const int lane  = tid & 31;
    const int wid   = tid >> 5;            // warp 0..7 -> rows [16w, 16w+16)
    const int r0    = wid * STRIP;
    const int cb    = lane << 2;           // first of this lane's 4 columns

    const float* tp = targ + (size_t)plane * (H * W) + cb;
    const float* pp = pred + (size_t)plane * (H * W) + cb;

    // Ring init: hm0 = hmax(row r0-1 clamped), hm1/v1 = row r0
    int gm1 = max(r0 - 1, 0);
    float4 vm1 = *reinterpret_cast<const float4*>(tp + gm1 * W);
    float4 hm0 = hmax4_warp(vm1, lane);
    float4 v1  = *reinterpret_cast<const float4*>(tp + r0 * W);
    float4 hm1 = hmax4_warp(v1, lane);

    float acc = 0.0f;

    #pragma unroll 4
    for (int k = 0; k < STRIP; k++) {
        int g2 = min(r0 + k + 1, H - 1);   // row below (clamped at plane bottom)
        float4 v2 = *reinterpret_cast<const float4*>(tp + g2 * W);
        float4 p  = *reinterpret_cast<const float4*>(pp + (r0 + k) * W);

        float4 hm2 = hmax4_warp(v2, lane);

        float dx = fmaxf(fmaxf(hm0.x, hm1.x), hm2.x);
        float dy = fmaxf(fmaxf(hm0.y, hm1.y), hm2.y);
        float dz = fmaxf(fmaxf(hm0.z, hm1.z), hm2.z);
        float dw = fmaxf(fmaxf(hm0.w, hm1.w), hm2.w);

        float lx = awing_elem(p.x, v1.x);
        float ly = awing_elem(p.y, v1.y);
        float lz = awing_elem(p.z, v1.z);
        float lw = awing_elem(p.w, v1.w);

        acc += lx * ((dx > MASK_THRESHOLD) ? 11.0f : 1.0f);
        acc += ly * ((dy > MASK_THRESHOLD) ? 11.0f : 1.0f);
        acc += lz * ((dz > MASK_THRESHOLD) ? 11.0f : 1.0f);
        acc += lw * ((dw > MASK_THRESHOLD) ? 11.0f : 1.0f);

        hm0 = hm1; hm1 = hm2; v1 = v2;
    }

    // ---- deterministic block reduction ----
    #pragma unroll
    for (int o = 16; o; o >>= 1)
        acc += __shfl_down_sync(FULL, acc, o);
    if (lane == 0) ws[wid] = acc;
    __syncthreads();
    if (tid == 0) {
        float t = ((ws[0] + ws[1]) + (ws[2] + ws[3]))
                + ((ws[4] + ws[5]) + (ws[6] + ws[7]));
        g_partials[plane] = t;
    }
}

__global__ __launch_bounds__(256)
void awing_final_kernel(float* __restrict__ out)
{
    __shared__ double sd[8];
    double a = 0.0;
    const float4* gp4 = reinterpret_cast<const float4*>(g_partials);
    #pragma unroll
    for (int i = threadIdx.x; i < NPLANES / 4; i += 256) {
        float4 v = gp4[i];
        a += (double)v.x + (double)v.y + (double)v.z + (double)v.w;
    }
    #pragma unroll
    for (int o = 16; o; o >>= 1)
        a += __shfl_down_sync(FULL, a, o);
    if ((threadIdx.x & 31) == 0) sd[threadIdx.x >> 5] = a;
    __syncthreads();
    if (threadIdx.x == 0) {
        double t = ((sd[0] + sd[1]) + (sd[2] + sd[3]))
                 + ((sd[4] + sd[5]) + (sd[6] + sd[7]));
        out[0] = (float)(t / N_ELEMS);
    }
}

extern "C" void kernel_launch(void* const* d_in, const int* in_sizes, int n_in,
                              void* d_out, int out_size)
{
    const float* pred = (const float*)d_in[0];
    const float* targ = (const float*)d_in[1];

    awing_main_kernel<<<NPLANES, 256>>>(pred, targ);
    awing_final_kernel<<<1, 256>>>((float*)d_out);
}